// round 15
// baseline (speedup 1.0000x reference)
#include <cuda_runtime.h>

#define NEPS 1e-20f

static constexpr int BB = 16;
static constexpr int H0 = 512, W0 = 640;
static constexpr int FULLN  = BB * 2 * H0 * W0;
static constexpr int HALFN  = BB * 2 * (H0/2) * (W0/2);
static constexpr int QUARTN = BB * 2 * (H0/4) * (W0/4);
static constexpr int EIGHTN = BB * 2 * (H0/8) * (W0/8);

// Scratch (static __device__ — no allocation APIs allowed)
__device__ float g_fx_a[FULLN];
__device__ float g_fc_a[FULLN];
__device__ float g_fx_b[FULLN];
__device__ float g_fc_b[FULLN];
__device__ float g_hx_a[HALFN];
__device__ float g_hc_a[HALFN];
__device__ float g_hx_b[HALFN];
__device__ float g_hc_b[HALFN];
__device__ float g_qx_a[QUARTN];
__device__ float g_qc_a[QUARTN];
__device__ float g_qx_b[QUARTN];
__device__ float g_qc_b[QUARTN];
__device__ float g_ex_a[EIGHTN];
__device__ float g_ec_a[EIGHTN];
__device__ float g_ex_b[EIGHTN];
__device__ float g_ec_b[EIGHTN];

// Packed duplicated weights (w,w), ky-outer layout:
//  5x5 layer: [ci][ky] -> 12 pairs: co0 kx0..4,pad ; co1 kx0..4,pad
//  3x3 layer: [ci][ky] -> 8 pairs:  co0 kx0..2,pad ; co1 kx0..2,pad
// Offsets (pairs): w1:0(60) w2:60(120) w3:180(120) w34:300(96) w23:396(96)
//                  w12:492(96) w4:588(2)
__constant__ unsigned long long g_wc[640];
__device__   unsigned long long g_wstage[640];
__device__   float2             g_brs[16];   // (bias, 1/sum(w)) per (layer, co)

__device__ __forceinline__ void ffma2(unsigned long long& a,
                                      unsigned long long w,
                                      unsigned long long v) {
    asm("fma.rn.f32x2 %0, %1, %2, %0;" : "+l"(a) : "l"(w), "l"(v));
}
__device__ __forceinline__ float2 unpk(unsigned long long v) {
    float2 r;
    asm("mov.b64 {%0, %1}, %2;" : "=f"(r.x), "=f"(r.y) : "l"(v));
    return r;
}
__device__ __forceinline__ unsigned long long dup(float w) {
    return (unsigned long long)__float_as_uint(w) * 0x100000001ULL;
}

// ---------------------------------------------------------------------------
// prep: build ky-outer weight layout + (bias, 1/sum(w)) table.
// ---------------------------------------------------------------------------
__global__ void prep_kernel(
    const float* __restrict__ w1,  const float* __restrict__ w2,
    const float* __restrict__ w3,  const float* __restrict__ w34,
    const float* __restrict__ w23, const float* __restrict__ w12,
    const float* __restrict__ w4,
    const float* __restrict__ b1,  const float* __restrict__ b2,
    const float* __restrict__ b3,  const float* __restrict__ b34,
    const float* __restrict__ b23, const float* __restrict__ b12,
    const float* __restrict__ b4)
{
    int t = threadIdx.x;
    if (t < 640) {
        unsigned long long val = 0ULL;
        if (t < 60) {                       // w1: CI=1, 5x5
            int l = t, g = l / 12, s = l % 12;
            int ci = g / 5, ky = g % 5, co = s / 6, kx = s % 6;
            if (kx < 5) val = dup(w1[((co * 1 + ci) * 5 + ky) * 5 + kx]);
        } else if (t < 180) {               // w2: CI=2, 5x5
            int l = t - 60, g = l / 12, s = l % 12;
            int ci = g / 5, ky = g % 5, co = s / 6, kx = s % 6;
            if (kx < 5) val = dup(w2[((co * 2 + ci) * 5 + ky) * 5 + kx]);
        } else if (t < 300) {               // w3: CI=2, 5x5
            int l = t - 180, g = l / 12, s = l % 12;
            int ci = g / 5, ky = g % 5, co = s / 6, kx = s % 6;
            if (kx < 5) val = dup(w3[((co * 2 + ci) * 5 + ky) * 5 + kx]);
        } else if (t < 396) {               // w34: CI=4, 3x3
            int l = t - 300, g = l / 8, s = l % 8;
            int ci = g / 3, ky = g % 3, co = s / 4, kx = s % 4;
            if (kx < 3) val = dup(w34[((co * 4 + ci) * 3 + ky) * 3 + kx]);
        } else if (t < 492) {               // w23
            int l = t - 396, g = l / 8, s = l % 8;
            int ci = g / 3, ky = g % 3, co = s / 4, kx = s % 4;
            if (kx < 3) val = dup(w23[((co * 4 + ci) * 3 + ky) * 3 + kx]);
        } else if (t < 588) {               // w12
            int l = t - 492, g = l / 8, s = l % 8;
            int ci = g / 3, ky = g % 3, co = s / 4, kx = s % 4;
            if (kx < 3) val = dup(w12[((co * 4 + ci) * 3 + ky) * 3 + kx]);
        } else if (t < 590) {               // w4
            val = dup(w4[t - 588]);
        }
        g_wstage[t] = val;
    }
    if (t < 13) {   // 6 layers x 2 co + w4 (co=0 only)
        const float* ws[7] = {w1, w2, w3, w34, w23, w12, w4};
        int L = t >> 1, co = t & 1;
        const int cnt[7] = {25, 50, 50, 36, 36, 36, 2};
        const float* bs[7] = {b1, b2, b3, b34, b23, b12, b4};
        float s = 0.f;
        const float* wp = ws[L] + co * cnt[L];
        for (int i = 0; i < cnt[L]; i++) s += wp[i];
        g_brs[t] = make_float2(bs[L][co], 1.f / s);
    }
}

// ---------------------------------------------------------------------------
// 5x5 navg, CO=2, ky-outer with PER-CO weight batches. (256,7): 36-reg cap
// probe — ptxas beat the 42 cap by 2 (46->40), testing whether a further
// 4-reg remat squeeze holds without mainloop spills. 56 warps/SM if it fits.
// 2x2 micro-tile, 32x32 block.
// ---------------------------------------------------------------------------
template<int CI, bool POOL>
__global__ void __launch_bounds__(256, 7)
navg5(const float* __restrict__ xin, const float* __restrict__ cin,
      int woff, int brsoff,
      float* __restrict__ xout, float* __restrict__ cout,
      float* __restrict__ xpool, float* __restrict__ cpool,
      int H, int W)
{
    constexpr int SH = 36, SW = 36;   // 32+4 rows, 32+4 pair-cols
    constexpr int SW2 = SW / 2;       // float2 chunks per row
    __shared__ __align__(16) unsigned long long sm[CI][SH][SW];

    const int tid = threadIdx.x;
    const int tx  = tid & 15, ty = tid >> 4;
    const int b   = blockIdx.z;
    const int gx0 = blockIdx.x * 32 - 2;   // even
    const int gy0 = blockIdx.y * 32 - 2;

    for (int i = tid; i < CI * SH * SW2; i += 256) {
        int ci = i / (SH * SW2), rem = i % (SH * SW2);
        int ly = rem / SW2, p2 = rem % SW2;
        int gy = gy0 + ly, gx = gx0 + 2 * p2;
        float2 xv = make_float2(0.f, 0.f), cv = make_float2(0.f, 0.f);
        if ((unsigned)gy < (unsigned)H && (unsigned)gx < (unsigned)W) {
            int o = ((b * CI + ci) * H + gy) * W + gx;
            xv = *(const float2*)&xin[o];
            cv = *(const float2*)&cin[o];
        }
        float4 pk = make_float4(xv.x * cv.x, cv.x, xv.y * cv.y, cv.y);
        *(float4*)&sm[ci][ly][2 * p2] = pk;
    }
    __syncthreads();

    unsigned long long acc[2][2][2];   // [oy][xpos][co], lanes = (xa, ca)
    #pragma unroll
    for (int i = 0; i < 2; i++)
        #pragma unroll
        for (int j = 0; j < 2; j++)
            #pragma unroll
            for (int k = 0; k < 2; k++) acc[i][j][k] = 0ULL;

    #pragma unroll
    for (int ci = 0; ci < CI; ci++) {
        #pragma unroll
        for (int ky = 0; ky < 5; ky++) {
            #pragma unroll
            for (int co = 0; co < 2; co++) {
                const unsigned long long* wp =
                    &g_wc[woff + (ci * 5 + ky) * 12 + co * 6];
                ulonglong2 w01 = *(const ulonglong2*)wp;
                ulonglong2 w23 = *(const ulonglong2*)(wp + 2);
                unsigned long long w4 = wp[4];
                #pragma unroll
                for (int oy = 0; oy < 2; oy++) {
                    const unsigned long long* rp =
                        &sm[ci][2 * ty + oy + ky][2 * tx];
                    ulonglong2 p0 = *(const ulonglong2*)rp;
                    ulonglong2 p1 = *(const ulonglong2*)(rp + 2);
                    ulonglong2 p2 = *(const ulonglong2*)(rp + 4);
                    ffma2(acc[oy][0][co], w01.x, p0.x);
                    ffma2(acc[oy][1][co], w01.x, p0.y);
                    ffma2(acc[oy][0][co], w01.y, p0.y);
                    ffma2(acc[oy][1][co], w01.y, p1.x);
                    ffma2(acc[oy][0][co], w23.x, p1.x);
                    ffma2(acc[oy][1][co], w23.x, p1.y);
                    ffma2(acc[oy][0][co], w23.y, p1.y);
                    ffma2(acc[oy][1][co], w23.y, p2.x);
                    ffma2(acc[oy][0][co], w4,    p2.x);
                    ffma2(acc[oy][1][co], w4,    p2.y);
                }
            }
        }
    }

    const float2 brs0 = g_brs[brsoff];
    const float2 brs1 = g_brs[brsoff + 1];
    const int ox0 = blockIdx.x * 32 + 2 * tx;
    const int oy0 = blockIdx.y * 32 + 2 * ty;

    float xov[2][2][2], cov[2][2][2];
    #pragma unroll
    for (int oy = 0; oy < 2; oy++)
        #pragma unroll
        for (int xp = 0; xp < 2; xp++)
            #pragma unroll
            for (int co = 0; co < 2; co++) {
                float2 u = unpk(acc[oy][xp][co]);
                float bx = co ? brs1.x : brs0.x;
                float rs = co ? brs1.y : brs0.y;
                xov[oy][xp][co] = __fdividef(u.x, u.y + NEPS) + bx;
                cov[oy][xp][co] = u.y * rs;
            }

    if (ox0 < W) {
        #pragma unroll
        for (int oy = 0; oy < 2; oy++) {
            int y = oy0 + oy;
            if (y < H) {
                #pragma unroll
                for (int co = 0; co < 2; co++) {
                    int o = ((b * 2 + co) * H + y) * W + ox0;
                    *(float2*)&xout[o] = make_float2(xov[oy][0][co], xov[oy][1][co]);
                    *(float2*)&cout[o] = make_float2(cov[oy][0][co], cov[oy][1][co]);
                }
            }
        }
        if (POOL && oy0 < H) {
            #pragma unroll
            for (int co = 0; co < 2; co++) {
                float bc = cov[0][0][co], bx = xov[0][0][co];
                if (cov[0][1][co] > bc) { bc = cov[0][1][co]; bx = xov[0][1][co]; }
                if (cov[1][0][co] > bc) { bc = cov[1][0][co]; bx = xov[1][0][co]; }
                if (cov[1][1][co] > bc) { bc = cov[1][1][co]; bx = xov[1][1][co]; }
                int o = ((b * 2 + co) * (H >> 1) + (oy0 >> 1)) * (W >> 1) + (ox0 >> 1);
                cpool[o] = bc * 0.25f;
                xpool[o] = bx;
            }
        }
    }
}

// ---------------------------------------------------------------------------
// concat(2ch, 2ch) -> 3x3 navg (CI=4). R-outer mainloop, per-co weight
// batches from constant. Pair-vectorized loader (even origin).
// Micro-tile 2x2; block 32x32. (256,6) — smem-limited to 5 CTAs anyway.
// FINAL: fuse trailing 1x1 navg (w4,b4); outputs 1ch x/c planes into d_out.
// ---------------------------------------------------------------------------
template<bool FINAL, int S1, int S2>
__global__ void __launch_bounds__(256, 6)
navg3cat(const float* __restrict__ x1, const float* __restrict__ c1,
         const float* __restrict__ x2, const float* __restrict__ c2,
         int woff, int brsoff,
         float* __restrict__ xout, float* __restrict__ cout,
         int H, int W)
{
    constexpr int CI = 4, SH = 34, SW = 36;
    constexpr int SW2 = SW / 2;
    __shared__ __align__(16) unsigned long long sm[CI][SH][SW];

    const int tid = threadIdx.x;
    const int tx  = tid & 15, ty = tid >> 4;
    const int b   = blockIdx.z;
    const int gx0 = blockIdx.x * 32 - 2;   // even
    const int gy0 = blockIdx.y * 32 - 1;

    for (int i = tid; i < CI * SH * SW2; i += 256) {
        int ci = i / (SH * SW2), rem = i % (SH * SW2);
        int ly = rem / SW2, p2 = rem % SW2;
        int gy = gy0 + ly, gx = gx0 + 2 * p2;   // gx even
        float2 xv = make_float2(0.f, 0.f), cv = make_float2(0.f, 0.f);
        if ((unsigned)gy < (unsigned)H && (unsigned)gx < (unsigned)W) {
            int cc = ci & 1;
            if (ci < 2) {
                if (S1 == 0) {
                    int o = ((b * 2 + cc) * H + gy) * W + gx;
                    xv = *(const float2*)&x1[o];
                    cv = *(const float2*)&c1[o];
                } else {
                    int o = ((b * 2 + cc) * (H >> 1) + (gy >> 1)) * (W >> 1) + (gx >> 1);
                    float xs = x1[o], cs = c1[o];
                    xv = make_float2(xs, xs); cv = make_float2(cs, cs);
                }
            } else {
                if (S2 == 0) {
                    int o = ((b * 2 + cc) * H + gy) * W + gx;
                    xv = *(const float2*)&x2[o];
                    cv = *(const float2*)&c2[o];
                } else {
                    int o = ((b * 2 + cc) * (H >> 1) + (gy >> 1)) * (W >> 1) + (gx >> 1);
                    float xs = x2[o], cs = c2[o];
                    xv = make_float2(xs, xs); cv = make_float2(cs, cs);
                }
            }
        }
        float4 pk = make_float4(xv.x * cv.x, cv.x, xv.y * cv.y, cv.y);
        *(float4*)&sm[ci][ly][2 * p2] = pk;
    }
    __syncthreads();

    unsigned long long acc[2][2][2];
    #pragma unroll
    for (int i = 0; i < 2; i++)
        #pragma unroll
        for (int j = 0; j < 2; j++)
            #pragma unroll
            for (int k = 0; k < 2; k++) acc[i][j][k] = 0ULL;

    // r-outer: row loaded once, used by every (ky, co) that touches it.
    // Inputs for output x = base+2tx+xp are local pairs (2tx+1+xp+kx).
    #pragma unroll
    for (int ci = 0; ci < 4; ci++) {
        #pragma unroll
        for (int r = 0; r < 4; r++) {
            const unsigned long long* rp = &sm[ci][2 * ty + r][2 * tx];
            ulonglong2 p0 = *(const ulonglong2*)rp;       // v0, v1
            ulonglong2 p1 = *(const ulonglong2*)(rp + 2); // v2, v3
            unsigned long long v4 = rp[4];
            #pragma unroll
            for (int ky = 0; ky < 3; ky++) {
                const int oy = r - ky;
                if (oy < 0 || oy > 1) continue;   // compile-time pruned
                #pragma unroll
                for (int co = 0; co < 2; co++) {
                    const unsigned long long* wp =
                        &g_wc[woff + (ci * 3 + ky) * 8 + co * 4];
                    ulonglong2 w01 = *(const ulonglong2*)wp;
                    unsigned long long w2 = wp[2];
                    ffma2(acc[oy][0][co], w01.x, p0.y);
                    ffma2(acc[oy][1][co], w01.x, p1.x);
                    ffma2(acc[oy][0][co], w01.y, p1.x);
                    ffma2(acc[oy][1][co], w01.y, p1.y);
                    ffma2(acc[oy][0][co], w2,    p1.y);
                    ffma2(acc[oy][1][co], w2,    v4);
                }
            }
        }
    }

    const float2 brs0 = g_brs[brsoff];
    const float2 brs1 = g_brs[brsoff + 1];
    const int ox0 = blockIdx.x * 32 + 2 * tx;
    const int oy0 = blockIdx.y * 32 + 2 * ty;

    float w40 = 0.f, w41 = 0.f; float2 brs4 = make_float2(0.f, 0.f);
    if (FINAL) {
        w40 = unpk(g_wc[588]).x;
        w41 = unpk(g_wc[589]).x;
        brs4 = g_brs[12];
    }

    if (ox0 < W) {
        #pragma unroll
        for (int oy = 0; oy < 2; oy++) {
            int y = oy0 + oy;
            if (y >= H) continue;

            float xo_[2][2], co_[2][2];   // [xp][co]
            #pragma unroll
            for (int xp = 0; xp < 2; xp++)
                #pragma unroll
                for (int co = 0; co < 2; co++) {
                    float2 u = unpk(acc[oy][xp][co]);
                    float bx = co ? brs1.x : brs0.x;
                    float rs = co ? brs1.y : brs0.y;
                    xo_[xp][co] = __fdividef(u.x, u.y + NEPS) + bx;
                    co_[xp][co] = u.y * rs;
                }

            if (FINAL) {
                float xf[2], cf[2];
                #pragma unroll
                for (int xp = 0; xp < 2; xp++) {
                    float a4 = w40 * co_[xp][0] + w41 * co_[xp][1];
                    float xn = w40 * (xo_[xp][0] * co_[xp][0]) +
                               w41 * (xo_[xp][1] * co_[xp][1]);
                    xf[xp] = __fdividef(xn, a4 + NEPS) + brs4.x;
                    cf[xp] = a4 * brs4.y;
                }
                int o = (b * H + y) * W + ox0;
                *(float2*)&xout[o] = make_float2(xf[0], xf[1]);
                *(float2*)&cout[o] = make_float2(cf[0], cf[1]);
            } else {
                #pragma unroll
                for (int co = 0; co < 2; co++) {
                    int o = ((b * 2 + co) * H + y) * W + ox0;
                    *(float2*)&xout[o] = make_float2(xo_[0][co], xo_[1][co]);
                    *(float2*)&cout[o] = make_float2(co_[0][co], co_[1][co]);
                }
            }
        }
    }
}

// ---------------------------------------------------------------------------
extern "C" void kernel_launch(void* const* d_in, const int* in_sizes, int n_in,
                              void* d_out, int out_size)
{
    (void)in_sizes; (void)n_in; (void)out_size;
    const float* x0  = (const float*)d_in[0];
    const float* c0  = (const float*)d_in[1];
    const float* w1  = (const float*)d_in[2];
    const float* w2  = (const float*)d_in[3];
    const float* w3  = (const float*)d_in[4];
    const float* w4  = (const float*)d_in[5];
    const float* w34 = (const float*)d_in[6];
    const float* w23 = (const float*)d_in[7];
    const float* w12 = (const float*)d_in[8];
    const float* b1  = (const float*)d_in[9];
    const float* b2  = (const float*)d_in[10];
    const float* b3  = (const float*)d_in[11];
    const float* b4  = (const float*)d_in[12];
    const float* b34 = (const float*)d_in[13];
    const float* b23 = (const float*)d_in[14];
    const float* b12 = (const float*)d_in[15];
    float* outp = (float*)d_out;

    float *fx_a, *fc_a, *fx_b, *fc_b;
    float *hx_a, *hc_a, *hx_b, *hc_b;
    float *qx_a, *qc_a, *qx_b, *qc_b;
    float *ex_a, *ec_a, *ex_b, *ec_b;
    cudaGetSymbolAddress((void**)&fx_a, g_fx_a);
    cudaGetSymbolAddress((void**)&fc_a, g_fc_a);
    cudaGetSymbolAddress((void**)&fx_b, g_fx_b);
    cudaGetSymbolAddress((void**)&fc_b, g_fc_b);
    cudaGetSymbolAddress((void**)&hx_a, g_hx_a);
    cudaGetSymbolAddress((void**)&hc_a, g_hc_a);
    cudaGetSymbolAddress((void**)&hx_b, g_hx_b);
    cudaGetSymbolAddress((void**)&hc_b, g_hc_b);
    cudaGetSymbolAddress((void**)&qx_a, g_qx_a);
    cudaGetSymbolAddress((void**)&qc_a, g_qc_a);
    cudaGetSymbolAddress((void**)&qx_b, g_qx_b);
    cudaGetSymbolAddress((void**)&qc_b, g_qc_b);
    cudaGetSymbolAddress((void**)&ex_a, g_ex_a);
    cudaGetSymbolAddress((void**)&ec_a, g_ec_a);
    cudaGetSymbolAddress((void**)&ex_b, g_ex_b);
    cudaGetSymbolAddress((void**)&ec_b, g_ec_b);

    void* wc_ptr;     cudaGetSymbolAddress(&wc_ptr, g_wc);
    void* stage_ptr;  cudaGetSymbolAddress(&stage_ptr, g_wstage);

    prep_kernel<<<1, 640>>>(w1, w2, w3, w34, w23, w12, w4,
                            b1, b2, b3, b34, b23, b12, b4);
    cudaMemcpyAsync(wc_ptr, stage_ptr, 640 * sizeof(unsigned long long),
                    cudaMemcpyDeviceToDevice, 0);

    auto g3 = [](int W, int H) { return dim3((W + 31) / 32, (H + 31) / 32, BB); };

    // L1: navg(w1, c0, x0)  full, CI=1
    navg5<1, false><<<g3(640, 512), 256>>>(x0, c0, 0, 0,
        fx_a, fc_a, nullptr, nullptr, 512, 640);
    // L2: navg(w2)  full
    navg5<2, false><<<g3(640, 512), 256>>>(fx_a, fc_a, 60, 2,
        fx_b, fc_b, nullptr, nullptr, 512, 640);
    // L3: navg(w3) -> (x1,c1) + fused pool -> half
    navg5<2, true><<<g3(640, 512), 256>>>(fx_b, fc_b, 180, 4,
        fx_a, fc_a, hx_a, hc_a, 512, 640);
    // L5: navg(w2)  half
    navg5<2, false><<<g3(320, 256), 256>>>(hx_a, hc_a, 60, 2,
        hx_b, hc_b, nullptr, nullptr, 256, 320);
    // L6: navg(w3) -> (x2_ds,c2_ds) + pool -> quarter
    navg5<2, true><<<g3(320, 256), 256>>>(hx_b, hc_b, 180, 4,
        hx_a, hc_a, qx_a, qc_a, 256, 320);
    // L8: navg(w2) -> (x3_ds,c3_ds) + pool -> eighth
    navg5<2, true><<<g3(160, 128), 256>>>(qx_a, qc_a, 60, 2,
        qx_b, qc_b, ex_a, ec_a, 128, 160);
    // L10: navg(w2) -> (x4_ds,c4_ds)  eighth
    navg5<2, false><<<g3(80, 64), 256>>>(ex_a, ec_a, 60, 2,
        ex_b, ec_b, nullptr, nullptr, 64, 80);
    // L12: navg(w34, cat(c3_ds, up2(c4_ds)))  quarter
    navg3cat<false, 0, 1><<<g3(160, 128), 256>>>(qx_b, qc_b, ex_b, ec_b,
        300, 6, qx_a, qc_a, 128, 160);
    // L14: navg(w23, cat(c2_ds, up2(c34_ds)))  half
    navg3cat<false, 0, 1><<<g3(320, 256), 256>>>(hx_a, hc_a, qx_a, qc_a,
        396, 8, hx_b, hc_b, 256, 320);
    // L16+L17: navg(w12, cat(up2(c23), c1)) + fused 1x1 navg(w4) -> d_out
    navg3cat<true, 1, 0><<<g3(640, 512), 256>>>(hx_b, hc_b, fx_a, fc_a,
        492, 10, outp, outp + (size_t)BB * H0 * W0, 512, 640);
}

// round 16
// speedup vs baseline: 1.0817x; 1.0817x over previous
#include <cuda_runtime.h>

#define NEPS 1e-20f

static constexpr int BB = 16;
static constexpr int H0 = 512, W0 = 640;
static constexpr int FULLN  = BB * 2 * H0 * W0;
static constexpr int HALFN  = BB * 2 * (H0/2) * (W0/2);
static constexpr int QUARTN = BB * 2 * (H0/4) * (W0/4);
static constexpr int EIGHTN = BB * 2 * (H0/8) * (W0/8);

// Scratch (static __device__ — no allocation APIs allowed)
__device__ float g_fx_a[FULLN];
__device__ float g_fc_a[FULLN];
__device__ float g_fx_b[FULLN];
__device__ float g_fc_b[FULLN];
__device__ float g_hx_a[HALFN];
__device__ float g_hc_a[HALFN];
__device__ float g_hx_b[HALFN];
__device__ float g_hc_b[HALFN];
__device__ float g_qx_a[QUARTN];
__device__ float g_qc_a[QUARTN];
__device__ float g_qx_b[QUARTN];
__device__ float g_qc_b[QUARTN];
__device__ float g_ex_a[EIGHTN];
__device__ float g_ec_a[EIGHTN];
__device__ float g_ex_b[EIGHTN];
__device__ float g_ec_b[EIGHTN];

// Packed duplicated weights (w,w), ky-outer layout:
//  5x5 layer: [ci][ky] -> 12 pairs: co0 kx0..4,pad ; co1 kx0..4,pad
//  3x3 layer: [ci][ky] -> 8 pairs:  co0 kx0..2,pad ; co1 kx0..2,pad
// Offsets (pairs): w1:0(60) w2:60(120) w3:180(120) w34:300(96) w23:396(96)
//                  w12:492(96) w4:588(2)
__constant__ unsigned long long g_wc[640];
__device__   unsigned long long g_wstage[640];
__device__   float2             g_brs[16];   // (bias, 1/sum(w)) per (layer, co)

__device__ __forceinline__ void ffma2(unsigned long long& a,
                                      unsigned long long w,
                                      unsigned long long v) {
    asm("fma.rn.f32x2 %0, %1, %2, %0;" : "+l"(a) : "l"(w), "l"(v));
}
__device__ __forceinline__ float2 unpk(unsigned long long v) {
    float2 r;
    asm("mov.b64 {%0, %1}, %2;" : "=f"(r.x), "=f"(r.y) : "l"(v));
    return r;
}
__device__ __forceinline__ unsigned long long dup(float w) {
    return (unsigned long long)__float_as_uint(w) * 0x100000001ULL;
}

// ---------------------------------------------------------------------------
// prep: build ky-outer weight layout + (bias, 1/sum(w)) table.
// ---------------------------------------------------------------------------
__global__ void prep_kernel(
    const float* __restrict__ w1,  const float* __restrict__ w2,
    const float* __restrict__ w3,  const float* __restrict__ w34,
    const float* __restrict__ w23, const float* __restrict__ w12,
    const float* __restrict__ w4,
    const float* __restrict__ b1,  const float* __restrict__ b2,
    const float* __restrict__ b3,  const float* __restrict__ b34,
    const float* __restrict__ b23, const float* __restrict__ b12,
    const float* __restrict__ b4)
{
    int t = threadIdx.x;
    if (t < 640) {
        unsigned long long val = 0ULL;
        if (t < 60) {                       // w1: CI=1, 5x5
            int l = t, g = l / 12, s = l % 12;
            int ci = g / 5, ky = g % 5, co = s / 6, kx = s % 6;
            if (kx < 5) val = dup(w1[((co * 1 + ci) * 5 + ky) * 5 + kx]);
        } else if (t < 180) {               // w2: CI=2, 5x5
            int l = t - 60, g = l / 12, s = l % 12;
            int ci = g / 5, ky = g % 5, co = s / 6, kx = s % 6;
            if (kx < 5) val = dup(w2[((co * 2 + ci) * 5 + ky) * 5 + kx]);
        } else if (t < 300) {               // w3: CI=2, 5x5
            int l = t - 180, g = l / 12, s = l % 12;
            int ci = g / 5, ky = g % 5, co = s / 6, kx = s % 6;
            if (kx < 5) val = dup(w3[((co * 2 + ci) * 5 + ky) * 5 + kx]);
        } else if (t < 396) {               // w34: CI=4, 3x3
            int l = t - 300, g = l / 8, s = l % 8;
            int ci = g / 3, ky = g % 3, co = s / 4, kx = s % 4;
            if (kx < 3) val = dup(w34[((co * 4 + ci) * 3 + ky) * 3 + kx]);
        } else if (t < 492) {               // w23
            int l = t - 396, g = l / 8, s = l % 8;
            int ci = g / 3, ky = g % 3, co = s / 4, kx = s % 4;
            if (kx < 3) val = dup(w23[((co * 4 + ci) * 3 + ky) * 3 + kx]);
        } else if (t < 588) {               // w12
            int l = t - 492, g = l / 8, s = l % 8;
            int ci = g / 3, ky = g % 3, co = s / 4, kx = s % 4;
            if (kx < 3) val = dup(w12[((co * 4 + ci) * 3 + ky) * 3 + kx]);
        } else if (t < 590) {               // w4
            val = dup(w4[t - 588]);
        }
        g_wstage[t] = val;
    }
    if (t < 13) {   // 6 layers x 2 co + w4 (co=0 only)
        const float* ws[7] = {w1, w2, w3, w34, w23, w12, w4};
        int L = t >> 1, co = t & 1;
        const int cnt[7] = {25, 50, 50, 36, 36, 36, 2};
        const float* bs[7] = {b1, b2, b3, b34, b23, b12, b4};
        float s = 0.f;
        const float* wp = ws[L] + co * cnt[L];
        for (int i = 0; i < cnt[L]; i++) s += wp[i];
        g_brs[t] = make_float2(bs[L][co], 1.f / s);
    }
}

// ---------------------------------------------------------------------------
// 5x5 navg, CO=2, ky-outer with PER-CO weight batches (R13 validated optimum:
// regs 40, occ 68%, issue 54%, no spills — the 42-reg cap is the liveness
// floor; cap 7 proven to spill in R15). Weights from constant (vector LDC).
// 2x2 micro-tile, 32x32 block, (256,6).
// ---------------------------------------------------------------------------
template<int CI, bool POOL>
__global__ void __launch_bounds__(256, 6)
navg5(const float* __restrict__ xin, const float* __restrict__ cin,
      int woff, int brsoff,
      float* __restrict__ xout, float* __restrict__ cout,
      float* __restrict__ xpool, float* __restrict__ cpool,
      int H, int W)
{
    constexpr int SH = 36, SW = 36;   // 32+4 rows, 32+4 pair-cols
    constexpr int SW2 = SW / 2;       // float2 chunks per row
    __shared__ __align__(16) unsigned long long sm[CI][SH][SW];

    const int tid = threadIdx.x;
    const int tx  = tid & 15, ty = tid >> 4;
    const int b   = blockIdx.z;
    const int gx0 = blockIdx.x * 32 - 2;   // even
    const int gy0 = blockIdx.y * 32 - 2;

    for (int i = tid; i < CI * SH * SW2; i += 256) {
        int ci = i / (SH * SW2), rem = i % (SH * SW2);
        int ly = rem / SW2, p2 = rem % SW2;
        int gy = gy0 + ly, gx = gx0 + 2 * p2;
        float2 xv = make_float2(0.f, 0.f), cv = make_float2(0.f, 0.f);
        if ((unsigned)gy < (unsigned)H && (unsigned)gx < (unsigned)W) {
            int o = ((b * CI + ci) * H + gy) * W + gx;
            xv = *(const float2*)&xin[o];
            cv = *(const float2*)&cin[o];
        }
        float4 pk = make_float4(xv.x * cv.x, cv.x, xv.y * cv.y, cv.y);
        *(float4*)&sm[ci][ly][2 * p2] = pk;
    }
    __syncthreads();

    unsigned long long acc[2][2][2];   // [oy][xpos][co], lanes = (xa, ca)
    #pragma unroll
    for (int i = 0; i < 2; i++)
        #pragma unroll
        for (int j = 0; j < 2; j++)
            #pragma unroll
            for (int k = 0; k < 2; k++) acc[i][j][k] = 0ULL;

    #pragma unroll
    for (int ci = 0; ci < CI; ci++) {
        #pragma unroll
        for (int ky = 0; ky < 5; ky++) {
            #pragma unroll
            for (int co = 0; co < 2; co++) {
                const unsigned long long* wp =
                    &g_wc[woff + (ci * 5 + ky) * 12 + co * 6];
                ulonglong2 w01 = *(const ulonglong2*)wp;
                ulonglong2 w23 = *(const ulonglong2*)(wp + 2);
                unsigned long long w4 = wp[4];
                #pragma unroll
                for (int oy = 0; oy < 2; oy++) {
                    const unsigned long long* rp =
                        &sm[ci][2 * ty + oy + ky][2 * tx];
                    ulonglong2 p0 = *(const ulonglong2*)rp;
                    ulonglong2 p1 = *(const ulonglong2*)(rp + 2);
                    ulonglong2 p2 = *(const ulonglong2*)(rp + 4);
                    ffma2(acc[oy][0][co], w01.x, p0.x);
                    ffma2(acc[oy][1][co], w01.x, p0.y);
                    ffma2(acc[oy][0][co], w01.y, p0.y);
                    ffma2(acc[oy][1][co], w01.y, p1.x);
                    ffma2(acc[oy][0][co], w23.x, p1.x);
                    ffma2(acc[oy][1][co], w23.x, p1.y);
                    ffma2(acc[oy][0][co], w23.y, p1.y);
                    ffma2(acc[oy][1][co], w23.y, p2.x);
                    ffma2(acc[oy][0][co], w4,    p2.x);
                    ffma2(acc[oy][1][co], w4,    p2.y);
                }
            }
        }
    }

    const float2 brs0 = g_brs[brsoff];
    const float2 brs1 = g_brs[brsoff + 1];
    const int ox0 = blockIdx.x * 32 + 2 * tx;
    const int oy0 = blockIdx.y * 32 + 2 * ty;

    float xov[2][2][2], cov[2][2][2];
    #pragma unroll
    for (int oy = 0; oy < 2; oy++)
        #pragma unroll
        for (int xp = 0; xp < 2; xp++)
            #pragma unroll
            for (int co = 0; co < 2; co++) {
                float2 u = unpk(acc[oy][xp][co]);
                float bx = co ? brs1.x : brs0.x;
                float rs = co ? brs1.y : brs0.y;
                xov[oy][xp][co] = __fdividef(u.x, u.y + NEPS) + bx;
                cov[oy][xp][co] = u.y * rs;
            }

    if (ox0 < W) {
        #pragma unroll
        for (int oy = 0; oy < 2; oy++) {
            int y = oy0 + oy;
            if (y < H) {
                #pragma unroll
                for (int co = 0; co < 2; co++) {
                    int o = ((b * 2 + co) * H + y) * W + ox0;
                    *(float2*)&xout[o] = make_float2(xov[oy][0][co], xov[oy][1][co]);
                    *(float2*)&cout[o] = make_float2(cov[oy][0][co], cov[oy][1][co]);
                }
            }
        }
        if (POOL && oy0 < H) {
            #pragma unroll
            for (int co = 0; co < 2; co++) {
                float bc = cov[0][0][co], bx = xov[0][0][co];
                if (cov[0][1][co] > bc) { bc = cov[0][1][co]; bx = xov[0][1][co]; }
                if (cov[1][0][co] > bc) { bc = cov[1][0][co]; bx = xov[1][0][co]; }
                if (cov[1][1][co] > bc) { bc = cov[1][1][co]; bx = xov[1][1][co]; }
                int o = ((b * 2 + co) * (H >> 1) + (oy0 >> 1)) * (W >> 1) + (ox0 >> 1);
                cpool[o] = bc * 0.25f;
                xpool[o] = bx;
            }
        }
    }
}

// ---------------------------------------------------------------------------
// concat(2ch, 2ch) -> 3x3 navg (CI=4), ky-outer, PER-CO weight batches
// (3 pairs live). Pair-vectorized loader (even origin, SW=36):
//   shift==0 source: aligned float2 loads; shift==1: one load fills pair.
// Micro-tile 2x2; block 32x32. (256,6). R13 validated shape.
// FINAL: fuse trailing 1x1 navg (w4,b4); outputs 1ch x/c planes into d_out.
// ---------------------------------------------------------------------------
template<bool FINAL, int S1, int S2>
__global__ void __launch_bounds__(256, 6)
navg3cat(const float* __restrict__ x1, const float* __restrict__ c1,
         const float* __restrict__ x2, const float* __restrict__ c2,
         int woff, int brsoff,
         float* __restrict__ xout, float* __restrict__ cout,
         int H, int W)
{
    constexpr int CI = 4, SH = 34, SW = 36;
    constexpr int SW2 = SW / 2;
    __shared__ __align__(16) unsigned long long sm[CI][SH][SW];

    const int tid = threadIdx.x;
    const int tx  = tid & 15, ty = tid >> 4;
    const int b   = blockIdx.z;
    const int gx0 = blockIdx.x * 32 - 2;   // even
    const int gy0 = blockIdx.y * 32 - 1;

    for (int i = tid; i < CI * SH * SW2; i += 256) {
        int ci = i / (SH * SW2), rem = i % (SH * SW2);
        int ly = rem / SW2, p2 = rem % SW2;
        int gy = gy0 + ly, gx = gx0 + 2 * p2;   // gx even
        float2 xv = make_float2(0.f, 0.f), cv = make_float2(0.f, 0.f);
        if ((unsigned)gy < (unsigned)H && (unsigned)gx < (unsigned)W) {
            int cc = ci & 1;
            if (ci < 2) {
                if (S1 == 0) {
                    int o = ((b * 2 + cc) * H + gy) * W + gx;
                    xv = *(const float2*)&x1[o];
                    cv = *(const float2*)&c1[o];
                } else {
                    int o = ((b * 2 + cc) * (H >> 1) + (gy >> 1)) * (W >> 1) + (gx >> 1);
                    float xs = x1[o], cs = c1[o];
                    xv = make_float2(xs, xs); cv = make_float2(cs, cs);
                }
            } else {
                if (S2 == 0) {
                    int o = ((b * 2 + cc) * H + gy) * W + gx;
                    xv = *(const float2*)&x2[o];
                    cv = *(const float2*)&c2[o];
                } else {
                    int o = ((b * 2 + cc) * (H >> 1) + (gy >> 1)) * (W >> 1) + (gx >> 1);
                    float xs = x2[o], cs = c2[o];
                    xv = make_float2(xs, xs); cv = make_float2(cs, cs);
                }
            }
        }
        float4 pk = make_float4(xv.x * cv.x, cv.x, xv.y * cv.y, cv.y);
        *(float4*)&sm[ci][ly][2 * p2] = pk;
    }
    __syncthreads();

    unsigned long long acc[2][2][2];
    #pragma unroll
    for (int i = 0; i < 2; i++)
        #pragma unroll
        for (int j = 0; j < 2; j++)
            #pragma unroll
            for (int k = 0; k < 2; k++) acc[i][j][k] = 0ULL;

    // Inputs for output x = base+2tx+xp are local pairs (2tx+1+xp+kx).
    #pragma unroll
    for (int ci = 0; ci < 4; ci++) {
        #pragma unroll
        for (int ky = 0; ky < 3; ky++) {
            #pragma unroll
            for (int co = 0; co < 2; co++) {
                const unsigned long long* wp =
                    &g_wc[woff + (ci * 3 + ky) * 8 + co * 4];
                ulonglong2 w01 = *(const ulonglong2*)wp;
                unsigned long long w2 = wp[2];
                #pragma unroll
                for (int oy = 0; oy < 2; oy++) {
                    const unsigned long long* rp =
                        &sm[ci][2 * ty + oy + ky][2 * tx];
                    ulonglong2 p0 = *(const ulonglong2*)rp;       // v0, v1
                    ulonglong2 p1 = *(const ulonglong2*)(rp + 2); // v2, v3
                    unsigned long long v4 = rp[4];
                    ffma2(acc[oy][0][co], w01.x, p0.y);
                    ffma2(acc[oy][1][co], w01.x, p1.x);
                    ffma2(acc[oy][0][co], w01.y, p1.x);
                    ffma2(acc[oy][1][co], w01.y, p1.y);
                    ffma2(acc[oy][0][co], w2,    p1.y);
                    ffma2(acc[oy][1][co], w2,    v4);
                }
            }
        }
    }

    const float2 brs0 = g_brs[brsoff];
    const float2 brs1 = g_brs[brsoff + 1];
    const int ox0 = blockIdx.x * 32 + 2 * tx;
    const int oy0 = blockIdx.y * 32 + 2 * ty;

    float w40 = 0.f, w41 = 0.f; float2 brs4 = make_float2(0.f, 0.f);
    if (FINAL) {
        w40 = unpk(g_wc[588]).x;
        w41 = unpk(g_wc[589]).x;
        brs4 = g_brs[12];
    }

    if (ox0 < W) {
        #pragma unroll
        for (int oy = 0; oy < 2; oy++) {
            int y = oy0 + oy;
            if (y >= H) continue;

            float xo_[2][2], co_[2][2];   // [xp][co]
            #pragma unroll
            for (int xp = 0; xp < 2; xp++)
                #pragma unroll
                for (int co = 0; co < 2; co++) {
                    float2 u = unpk(acc[oy][xp][co]);
                    float bx = co ? brs1.x : brs0.x;
                    float rs = co ? brs1.y : brs0.y;
                    xo_[xp][co] = __fdividef(u.x, u.y + NEPS) + bx;
                    co_[xp][co] = u.y * rs;
                }

            if (FINAL) {
                float xf[2], cf[2];
                #pragma unroll
                for (int xp = 0; xp < 2; xp++) {
                    float a4 = w40 * co_[xp][0] + w41 * co_[xp][1];
                    float xn = w40 * (xo_[xp][0] * co_[xp][0]) +
                               w41 * (xo_[xp][1] * co_[xp][1]);
                    xf[xp] = __fdividef(xn, a4 + NEPS) + brs4.x;
                    cf[xp] = a4 * brs4.y;
                }
                int o = (b * H + y) * W + ox0;
                *(float2*)&xout[o] = make_float2(xf[0], xf[1]);
                *(float2*)&cout[o] = make_float2(cf[0], cf[1]);
            } else {
                #pragma unroll
                for (int co = 0; co < 2; co++) {
                    int o = ((b * 2 + co) * H + y) * W + ox0;
                    *(float2*)&xout[o] = make_float2(xo_[0][co], xo_[1][co]);
                    *(float2*)&cout[o] = make_float2(co_[0][co], co_[1][co]);
                }
            }
        }
    }
}

// ---------------------------------------------------------------------------
extern "C" void kernel_launch(void* const* d_in, const int* in_sizes, int n_in,
                              void* d_out, int out_size)
{
    (void)in_sizes; (void)n_in; (void)out_size;
    const float* x0  = (const float*)d_in[0];
    const float* c0  = (const float*)d_in[1];
    const float* w1  = (const float*)d_in[2];
    const float* w2  = (const float*)d_in[3];
    const float* w3  = (const float*)d_in[4];
    const float* w4  = (const float*)d_in[5];
    const float* w34 = (const float*)d_in[6];
    const float* w23 = (const float*)d_in[7];
    const float* w12 = (const float*)d_in[8];
    const float* b1  = (const float*)d_in[9];
    const float* b2  = (const float*)d_in[10];
    const float* b3  = (const float*)d_in[11];
    const float* b4  = (const float*)d_in[12];
    const float* b34 = (const float*)d_in[13];
    const float* b23 = (const float*)d_in[14];
    const float* b12 = (const float*)d_in[15];
    float* outp = (float*)d_out;

    float *fx_a, *fc_a, *fx_b, *fc_b;
    float *hx_a, *hc_a, *hx_b, *hc_b;
    float *qx_a, *qc_a, *qx_b, *qc_b;
    float *ex_a, *ec_a, *ex_b, *ec_b;
    cudaGetSymbolAddress((void**)&fx_a, g_fx_a);
    cudaGetSymbolAddress((void**)&fc_a, g_fc_a);
    cudaGetSymbolAddress((void**)&fx_b, g_fx_b);
    cudaGetSymbolAddress((void**)&fc_b, g_fc_b);
    cudaGetSymbolAddress((void**)&hx_a, g_hx_a);
    cudaGetSymbolAddress((void**)&hc_a, g_hc_a);
    cudaGetSymbolAddress((void**)&hx_b, g_hx_b);
    cudaGetSymbolAddress((void**)&hc_b, g_hc_b);
    cudaGetSymbolAddress((void**)&qx_a, g_qx_a);
    cudaGetSymbolAddress((void**)&qc_a, g_qc_a);
    cudaGetSymbolAddress((void**)&qx_b, g_qx_b);
    cudaGetSymbolAddress((void**)&qc_b, g_qc_b);
    cudaGetSymbolAddress((void**)&ex_a, g_ex_a);
    cudaGetSymbolAddress((void**)&ec_a, g_ec_a);
    cudaGetSymbolAddress((void**)&ex_b, g_ex_b);
    cudaGetSymbolAddress((void**)&ec_b, g_ec_b);

    void* wc_ptr;     cudaGetSymbolAddress(&wc_ptr, g_wc);
    void* stage_ptr;  cudaGetSymbolAddress(&stage_ptr, g_wstage);

    prep_kernel<<<1, 640>>>(w1, w2, w3, w34, w23, w12, w4,
                            b1, b2, b3, b34, b23, b12, b4);
    cudaMemcpyAsync(wc_ptr, stage_ptr, 640 * sizeof(unsigned long long),
                    cudaMemcpyDeviceToDevice, 0);

    auto g3 = [](int W, int H) { return dim3((W + 31) / 32, (H + 31) / 32, BB); };

    // L1: navg(w1, c0, x0)  full, CI=1
    navg5<1, false><<<g3(640, 512), 256>>>(x0, c0, 0, 0,
        fx_a, fc_a, nullptr, nullptr, 512, 640);
    // L2: navg(w2)  full
    navg5<2, false><<<g3(640, 512), 256>>>(fx_a, fc_a, 60, 2,
        fx_b, fc_b, nullptr, nullptr, 512, 640);
    // L3: navg(w3) -> (x1,c1) + fused pool -> half
    navg5<2, true><<<g3(640, 512), 256>>>(fx_b, fc_b, 180, 4,
        fx_a, fc_a, hx_a, hc_a, 512, 640);
    // L5: navg(w2)  half
    navg5<2, false><<<g3(320, 256), 256>>>(hx_a, hc_a, 60, 2,
        hx_b, hc_b, nullptr, nullptr, 256, 320);
    // L6: navg(w3) -> (x2_ds,c2_ds) + pool -> quarter
    navg5<2, true><<<g3(320, 256), 256>>>(hx_b, hc_b, 180, 4,
        hx_a, hc_a, qx_a, qc_a, 256, 320);
    // L8: navg(w2) -> (x3_ds,c3_ds) + pool -> eighth
    navg5<2, true><<<g3(160, 128), 256>>>(qx_a, qc_a, 60, 2,
        qx_b, qc_b, ex_a, ec_a, 128, 160);
    // L10: navg(w2) -> (x4_ds,c4_ds)  eighth
    navg5<2, false><<<g3(80, 64), 256>>>(ex_a, ec_a, 60, 2,
        ex_b, ec_b, nullptr, nullptr, 64, 80);
    // L12: navg(w34, cat(c3_ds, up2(c4_ds)))  quarter
    navg3cat<false, 0, 1><<<g3(160, 128), 256>>>(qx_b, qc_b, ex_b, ec_b,
        300, 6, qx_a, qc_a, 128, 160);
    // L14: navg(w23, cat(c2_ds, up2(c34_ds)))  half
    navg3cat<false, 0, 1><<<g3(320, 256), 256>>>(hx_a, hc_a, qx_a, qc_a,
        396, 8, hx_b, hc_b, 256, 320);
    // L16+L17: navg(w12, cat(up2(c23), c1)) + fused 1x1 navg(w4) -> d_out
    navg3cat<true, 1, 0><<<g3(640, 512), 256>>>(hx_b, hc_b, fx_a, fc_a,
        492, 10, outp, outp + (size_t)BB * H0 * W0, 512, 640);
}

// round 17
// speedup vs baseline: 1.1938x; 1.1037x over previous
#include <cuda_runtime.h>

#define NEPS 1e-20f

static constexpr int BB = 16;
static constexpr int H0 = 512, W0 = 640;
static constexpr int FULLN  = BB * 2 * H0 * W0;
static constexpr int HALFN  = BB * 2 * (H0/2) * (W0/2);
static constexpr int QUARTN = BB * 2 * (H0/4) * (W0/4);
static constexpr int EIGHTN = BB * 2 * (H0/8) * (W0/8);

// Scratch (static __device__ — no allocation APIs allowed)
__device__ float g_fx_a[FULLN];
__device__ float g_fc_a[FULLN];
__device__ float g_fx_b[FULLN];
__device__ float g_fc_b[FULLN];
__device__ float g_hx_a[HALFN];
__device__ float g_hc_a[HALFN];
__device__ float g_hx_b[HALFN];
__device__ float g_hc_b[HALFN];
__device__ float g_qx_a[QUARTN];
__device__ float g_qc_a[QUARTN];
__device__ float g_qx_b[QUARTN];
__device__ float g_qc_b[QUARTN];
__device__ float g_ex_a[EIGHTN];
__device__ float g_ec_a[EIGHTN];
__device__ float g_ex_b[EIGHTN];
__device__ float g_ec_b[EIGHTN];

// Packed duplicated weights (w,w), ky-outer layout:
//  5x5 layer: [ci][ky] -> 12 pairs: co0 kx0..4,pad ; co1 kx0..4,pad
//  3x3 layer: [ci][ky] -> 8 pairs:  co0 kx0..2,pad ; co1 kx0..2,pad
// Offsets (pairs): w1:0(60) w2:60(120) w3:180(120) w34:300(96) w23:396(96)
//                  w12:492(96) w4:588(2)
__constant__ unsigned long long g_wc[640];
__device__   unsigned long long g_wstage[640];
__device__   float2             g_brs[16];   // (bias, 1/sum(w)) per (layer, co)

__device__ __forceinline__ void ffma2(unsigned long long& a,
                                      unsigned long long w,
                                      unsigned long long v) {
    asm("fma.rn.f32x2 %0, %1, %2, %0;" : "+l"(a) : "l"(w), "l"(v));
}
__device__ __forceinline__ float2 unpk(unsigned long long v) {
    float2 r;
    asm("mov.b64 {%0, %1}, %2;" : "=f"(r.x), "=f"(r.y) : "l"(v));
    return r;
}
__device__ __forceinline__ unsigned long long dup(float w) {
    return (unsigned long long)__float_as_uint(w) * 0x100000001ULL;
}

// ---------------------------------------------------------------------------
// prep: build ky-outer weight layout + (bias, 1/sum(w)) table.
// ---------------------------------------------------------------------------
__global__ void prep_kernel(
    const float* __restrict__ w1,  const float* __restrict__ w2,
    const float* __restrict__ w3,  const float* __restrict__ w34,
    const float* __restrict__ w23, const float* __restrict__ w12,
    const float* __restrict__ w4,
    const float* __restrict__ b1,  const float* __restrict__ b2,
    const float* __restrict__ b3,  const float* __restrict__ b34,
    const float* __restrict__ b23, const float* __restrict__ b12,
    const float* __restrict__ b4)
{
    int t = threadIdx.x;
    if (t < 640) {
        unsigned long long val = 0ULL;
        if (t < 60) {                       // w1: CI=1, 5x5
            int l = t, g = l / 12, s = l % 12;
            int ci = g / 5, ky = g % 5, co = s / 6, kx = s % 6;
            if (kx < 5) val = dup(w1[((co * 1 + ci) * 5 + ky) * 5 + kx]);
        } else if (t < 180) {               // w2: CI=2, 5x5
            int l = t - 60, g = l / 12, s = l % 12;
            int ci = g / 5, ky = g % 5, co = s / 6, kx = s % 6;
            if (kx < 5) val = dup(w2[((co * 2 + ci) * 5 + ky) * 5 + kx]);
        } else if (t < 300) {               // w3: CI=2, 5x5
            int l = t - 180, g = l / 12, s = l % 12;
            int ci = g / 5, ky = g % 5, co = s / 6, kx = s % 6;
            if (kx < 5) val = dup(w3[((co * 2 + ci) * 5 + ky) * 5 + kx]);
        } else if (t < 396) {               // w34: CI=4, 3x3
            int l = t - 300, g = l / 8, s = l % 8;
            int ci = g / 3, ky = g % 3, co = s / 4, kx = s % 4;
            if (kx < 3) val = dup(w34[((co * 4 + ci) * 3 + ky) * 3 + kx]);
        } else if (t < 492) {               // w23
            int l = t - 396, g = l / 8, s = l % 8;
            int ci = g / 3, ky = g % 3, co = s / 4, kx = s % 4;
            if (kx < 3) val = dup(w23[((co * 4 + ci) * 3 + ky) * 3 + kx]);
        } else if (t < 588) {               // w12
            int l = t - 492, g = l / 8, s = l % 8;
            int ci = g / 3, ky = g % 3, co = s / 4, kx = s % 4;
            if (kx < 3) val = dup(w12[((co * 4 + ci) * 3 + ky) * 3 + kx]);
        } else if (t < 590) {               // w4
            val = dup(w4[t - 588]);
        }
        g_wstage[t] = val;
    }
    if (t < 13) {   // 6 layers x 2 co + w4 (co=0 only)
        const float* ws[7] = {w1, w2, w3, w34, w23, w12, w4};
        int L = t >> 1, co = t & 1;
        const int cnt[7] = {25, 50, 50, 36, 36, 36, 2};
        const float* bs[7] = {b1, b2, b3, b34, b23, b12, b4};
        float s = 0.f;
        const float* wp = ws[L] + co * cnt[L];
        for (int i = 0; i < cnt[L]; i++) s += wp[i];
        g_brs[t] = make_float2(bs[L][co], 1.f / s);
    }
}

// ---------------------------------------------------------------------------
// 5x5 navg, CO=2, ky-outer with PER-CO weight batches (R13 validated optimum:
// regs 40, occ 68%, no spills). Weights from constant (vector LDC).
// 2x2 micro-tile, 32x32 block, (256,6). UNCHANGED from R13/R16.
// ---------------------------------------------------------------------------
template<int CI, bool POOL>
__global__ void __launch_bounds__(256, 6)
navg5(const float* __restrict__ xin, const float* __restrict__ cin,
      int woff, int brsoff,
      float* __restrict__ xout, float* __restrict__ cout,
      float* __restrict__ xpool, float* __restrict__ cpool,
      int H, int W)
{
    constexpr int SH = 36, SW = 36;   // 32+4 rows, 32+4 pair-cols
    constexpr int SW2 = SW / 2;       // float2 chunks per row
    __shared__ __align__(16) unsigned long long sm[CI][SH][SW];

    const int tid = threadIdx.x;
    const int tx  = tid & 15, ty = tid >> 4;
    const int b   = blockIdx.z;
    const int gx0 = blockIdx.x * 32 - 2;   // even
    const int gy0 = blockIdx.y * 32 - 2;

    for (int i = tid; i < CI * SH * SW2; i += 256) {
        int ci = i / (SH * SW2), rem = i % (SH * SW2);
        int ly = rem / SW2, p2 = rem % SW2;
        int gy = gy0 + ly, gx = gx0 + 2 * p2;
        float2 xv = make_float2(0.f, 0.f), cv = make_float2(0.f, 0.f);
        if ((unsigned)gy < (unsigned)H && (unsigned)gx < (unsigned)W) {
            int o = ((b * CI + ci) * H + gy) * W + gx;
            xv = *(const float2*)&xin[o];
            cv = *(const float2*)&cin[o];
        }
        float4 pk = make_float4(xv.x * cv.x, cv.x, xv.y * cv.y, cv.y);
        *(float4*)&sm[ci][ly][2 * p2] = pk;
    }
    __syncthreads();

    unsigned long long acc[2][2][2];   // [oy][xpos][co], lanes = (xa, ca)
    #pragma unroll
    for (int i = 0; i < 2; i++)
        #pragma unroll
        for (int j = 0; j < 2; j++)
            #pragma unroll
            for (int k = 0; k < 2; k++) acc[i][j][k] = 0ULL;

    #pragma unroll
    for (int ci = 0; ci < CI; ci++) {
        #pragma unroll
        for (int ky = 0; ky < 5; ky++) {
            #pragma unroll
            for (int co = 0; co < 2; co++) {
                const unsigned long long* wp =
                    &g_wc[woff + (ci * 5 + ky) * 12 + co * 6];
                ulonglong2 w01 = *(const ulonglong2*)wp;
                ulonglong2 w23 = *(const ulonglong2*)(wp + 2);
                unsigned long long w4 = wp[4];
                #pragma unroll
                for (int oy = 0; oy < 2; oy++) {
                    const unsigned long long* rp =
                        &sm[ci][2 * ty + oy + ky][2 * tx];
                    ulonglong2 p0 = *(const ulonglong2*)rp;
                    ulonglong2 p1 = *(const ulonglong2*)(rp + 2);
                    ulonglong2 p2 = *(const ulonglong2*)(rp + 4);
                    ffma2(acc[oy][0][co], w01.x, p0.x);
                    ffma2(acc[oy][1][co], w01.x, p0.y);
                    ffma2(acc[oy][0][co], w01.y, p0.y);
                    ffma2(acc[oy][1][co], w01.y, p1.x);
                    ffma2(acc[oy][0][co], w23.x, p1.x);
                    ffma2(acc[oy][1][co], w23.x, p1.y);
                    ffma2(acc[oy][0][co], w23.y, p1.y);
                    ffma2(acc[oy][1][co], w23.y, p2.x);
                    ffma2(acc[oy][0][co], w4,    p2.x);
                    ffma2(acc[oy][1][co], w4,    p2.y);
                }
            }
        }
    }

    const float2 brs0 = g_brs[brsoff];
    const float2 brs1 = g_brs[brsoff + 1];
    const int ox0 = blockIdx.x * 32 + 2 * tx;
    const int oy0 = blockIdx.y * 32 + 2 * ty;

    float xov[2][2][2], cov[2][2][2];
    #pragma unroll
    for (int oy = 0; oy < 2; oy++)
        #pragma unroll
        for (int xp = 0; xp < 2; xp++)
            #pragma unroll
            for (int co = 0; co < 2; co++) {
                float2 u = unpk(acc[oy][xp][co]);
                float bx = co ? brs1.x : brs0.x;
                float rs = co ? brs1.y : brs0.y;
                xov[oy][xp][co] = __fdividef(u.x, u.y + NEPS) + bx;
                cov[oy][xp][co] = u.y * rs;
            }

    if (ox0 < W) {
        #pragma unroll
        for (int oy = 0; oy < 2; oy++) {
            int y = oy0 + oy;
            if (y < H) {
                #pragma unroll
                for (int co = 0; co < 2; co++) {
                    int o = ((b * 2 + co) * H + y) * W + ox0;
                    *(float2*)&xout[o] = make_float2(xov[oy][0][co], xov[oy][1][co]);
                    *(float2*)&cout[o] = make_float2(cov[oy][0][co], cov[oy][1][co]);
                }
            }
        }
        if (POOL && oy0 < H) {
            #pragma unroll
            for (int co = 0; co < 2; co++) {
                float bc = cov[0][0][co], bx = xov[0][0][co];
                if (cov[0][1][co] > bc) { bc = cov[0][1][co]; bx = xov[0][1][co]; }
                if (cov[1][0][co] > bc) { bc = cov[1][0][co]; bx = xov[1][0][co]; }
                if (cov[1][1][co] > bc) { bc = cov[1][1][co]; bx = xov[1][1][co]; }
                int o = ((b * 2 + co) * (H >> 1) + (oy0 >> 1)) * (W >> 1) + (ox0 >> 1);
                cpool[o] = bc * 0.25f;
                xpool[o] = bx;
            }
        }
    }
}

// ---------------------------------------------------------------------------
// concat(full 2ch, up2(half 2ch)) -> 3x3 navg (CI=4), ky-outer, per-co
// weight batches. NEW: the upsampled source is stored COMPACTLY in smem
// (2x18x18 pairs, 5.2KB) instead of pre-duplicated (19.6KB) — total smem
// 24.8KB -> 6 CTAs/SM (was 5). Duplication is resolved by indexing:
//   src row for input row gy = gy>>1 -> smH row ty + ((oy+ky-1)>>1)+1
//   src col for input px  p  = p>>1  -> taps (h0,h1,h1) / (h1,h1,h2)
// UPFIRST: upsampled source is first in the concat (weight ci 0,1).
// FINAL: fuse trailing 1x1 navg (w4,b4); outputs 1ch x/c planes into d_out.
// ---------------------------------------------------------------------------
template<bool FINAL, bool UPFIRST>
__global__ void __launch_bounds__(256, 6)
navg3cat(const float* __restrict__ xF, const float* __restrict__ cF,
         const float* __restrict__ xU, const float* __restrict__ cU,
         int woff, int brsoff,
         float* __restrict__ xout, float* __restrict__ cout,
         int H, int W)
{
    __shared__ __align__(16) unsigned long long smF[2][34][36];
    __shared__ __align__(16) unsigned long long smH[2][18][18];

    const int tid = threadIdx.x;
    const int tx  = tid & 15, ty = tid >> 4;
    const int b   = blockIdx.z;
    const int gx0 = blockIdx.x * 32 - 2;   // even
    const int gy0 = blockIdx.y * 32 - 1;
    const int Hh  = H >> 1, Wh = W >> 1;
    const int hy0 = gy0 >> 1;              // 16*by - 1 (arithmetic shift)
    const int sx0 = gx0 >> 1;              // 16*bx - 1

    // full-res source: float2-vectorized, 2 px per iteration
    for (int i = tid; i < 2 * 34 * 18; i += 256) {
        int f = i / (34 * 18), rem = i % (34 * 18);
        int ly = rem / 18, c4 = rem % 18;
        int gy = gy0 + ly, gx = gx0 + 2 * c4;
        float2 xv = make_float2(0.f, 0.f), cv = make_float2(0.f, 0.f);
        if ((unsigned)gy < (unsigned)H && (unsigned)gx < (unsigned)W) {
            int o = ((b * 2 + f) * H + gy) * W + gx;
            xv = *(const float2*)&xF[o];
            cv = *(const float2*)&cF[o];
        }
        *(float4*)&smF[f][ly][2 * c4] =
            make_float4(xv.x * cv.x, cv.x, xv.y * cv.y, cv.y);
    }
    // half-res source: compact, one src pixel per pair
    for (int i = tid; i < 2 * 18 * 18; i += 256) {
        int u = i / (18 * 18), rem = i % (18 * 18);
        int r = rem / 18, p = rem % 18;
        int sy = hy0 + r, sx = sx0 + p;
        float xs = 0.f, cs = 0.f;
        if ((unsigned)sy < (unsigned)Hh && (unsigned)sx < (unsigned)Wh) {
            int o = ((b * 2 + u) * Hh + sy) * Wh + sx;
            xs = xU[o];
            cs = cU[o];
        }
        *(float2*)&smH[u][r][p] = make_float2(xs * cs, cs);
    }
    __syncthreads();

    unsigned long long acc[2][2][2];   // [oy][xp][co]
    #pragma unroll
    for (int i = 0; i < 2; i++)
        #pragma unroll
        for (int j = 0; j < 2; j++)
            #pragma unroll
            for (int k = 0; k < 2; k++) acc[i][j][k] = 0ULL;

    // full-res channels (inputs for x = base+2tx+xp are local px 2tx+1+xp+kx)
    #pragma unroll
    for (int f = 0; f < 2; f++) {
        const int wci = UPFIRST ? (2 + f) : f;
        #pragma unroll
        for (int ky = 0; ky < 3; ky++) {
            #pragma unroll
            for (int co = 0; co < 2; co++) {
                const unsigned long long* wp =
                    &g_wc[woff + (wci * 3 + ky) * 8 + co * 4];
                ulonglong2 w01 = *(const ulonglong2*)wp;
                unsigned long long w2 = wp[2];
                #pragma unroll
                for (int oy = 0; oy < 2; oy++) {
                    const unsigned long long* rp =
                        &smF[f][2 * ty + oy + ky][2 * tx];
                    ulonglong2 p0 = *(const ulonglong2*)rp;       // v0, v1
                    ulonglong2 p1 = *(const ulonglong2*)(rp + 2); // v2, v3
                    unsigned long long v4 = rp[4];
                    ffma2(acc[oy][0][co], w01.x, p0.y);
                    ffma2(acc[oy][1][co], w01.x, p1.x);
                    ffma2(acc[oy][0][co], w01.y, p1.x);
                    ffma2(acc[oy][1][co], w01.y, p1.y);
                    ffma2(acc[oy][0][co], w2,    p1.y);
                    ffma2(acc[oy][1][co], w2,    v4);
                }
            }
        }
    }

    // upsampled channels: smH rows ty+0..ty+2, cols tx+0..tx+2
    #pragma unroll
    for (int u = 0; u < 2; u++) {
        const int wci = UPFIRST ? u : (2 + u);
        #pragma unroll
        for (int r = 0; r < 3; r++) {
            unsigned long long h0 = smH[u][ty + r][tx];
            unsigned long long h1 = smH[u][ty + r][tx + 1];
            unsigned long long h2 = smH[u][ty + r][tx + 2];
            #pragma unroll
            for (int ky = 0; ky < 3; ky++) {
                #pragma unroll
                for (int oy = 0; oy < 2; oy++) {
                    if ((((oy + ky - 1) >> 1) + 1) != r) continue; // ct-pruned
                    #pragma unroll
                    for (int co = 0; co < 2; co++) {
                        const unsigned long long* wp =
                            &g_wc[woff + (wci * 3 + ky) * 8 + co * 4];
                        ulonglong2 w01 = *(const ulonglong2*)wp;
                        unsigned long long w2 = wp[2];
                        // xp=0 taps: h0, h1, h1 ; xp=1 taps: h1, h1, h2
                        ffma2(acc[oy][0][co], w01.x, h0);
                        ffma2(acc[oy][0][co], w01.y, h1);
                        ffma2(acc[oy][0][co], w2,    h1);
                        ffma2(acc[oy][1][co], w01.x, h1);
                        ffma2(acc[oy][1][co], w01.y, h1);
                        ffma2(acc[oy][1][co], w2,    h2);
                    }
                }
            }
        }
    }

    const float2 brs0 = g_brs[brsoff];
    const float2 brs1 = g_brs[brsoff + 1];
    const int ox0 = blockIdx.x * 32 + 2 * tx;
    const int oy0 = blockIdx.y * 32 + 2 * ty;

    float w40 = 0.f, w41 = 0.f; float2 brs4 = make_float2(0.f, 0.f);
    if (FINAL) {
        w40 = unpk(g_wc[588]).x;
        w41 = unpk(g_wc[589]).x;
        brs4 = g_brs[12];
    }

    if (ox0 < W) {
        #pragma unroll
        for (int oy = 0; oy < 2; oy++) {
            int y = oy0 + oy;
            if (y >= H) continue;

            float xo_[2][2], co_[2][2];   // [xp][co]
            #pragma unroll
            for (int xp = 0; xp < 2; xp++)
                #pragma unroll
                for (int co = 0; co < 2; co++) {
                    float2 u = unpk(acc[oy][xp][co]);
                    float bx = co ? brs1.x : brs0.x;
                    float rs = co ? brs1.y : brs0.y;
                    xo_[xp][co] = __fdividef(u.x, u.y + NEPS) + bx;
                    co_[xp][co] = u.y * rs;
                }

            if (FINAL) {
                float xf[2], cf[2];
                #pragma unroll
                for (int xp = 0; xp < 2; xp++) {
                    float a4 = w40 * co_[xp][0] + w41 * co_[xp][1];
                    float xn = w40 * (xo_[xp][0] * co_[xp][0]) +
                               w41 * (xo_[xp][1] * co_[xp][1]);
                    xf[xp] = __fdividef(xn, a4 + NEPS) + brs4.x;
                    cf[xp] = a4 * brs4.y;
                }
                int o = (b * H + y) * W + ox0;
                *(float2*)&xout[o] = make_float2(xf[0], xf[1]);
                *(float2*)&cout[o] = make_float2(cf[0], cf[1]);
            } else {
                #pragma unroll
                for (int co = 0; co < 2; co++) {
                    int o = ((b * 2 + co) * H + y) * W + ox0;
                    *(float2*)&xout[o] = make_float2(xo_[0][co], xo_[1][co]);
                    *(float2*)&cout[o] = make_float2(co_[0][co], co_[1][co]);
                }
            }
        }
    }
}

// ---------------------------------------------------------------------------
extern "C" void kernel_launch(void* const* d_in, const int* in_sizes, int n_in,
                              void* d_out, int out_size)
{
    (void)in_sizes; (void)n_in; (void)out_size;
    const float* x0  = (const float*)d_in[0];
    const float* c0  = (const float*)d_in[1];
    const float* w1  = (const float*)d_in[2];
    const float* w2  = (const float*)d_in[3];
    const float* w3  = (const float*)d_in[4];
    const float* w4  = (const float*)d_in[5];
    const float* w34 = (const float*)d_in[6];
    const float* w23 = (const float*)d_in[7];
    const float* w12 = (const float*)d_in[8];
    const float* b1  = (const float*)d_in[9];
    const float* b2  = (const float*)d_in[10];
    const float* b3  = (const float*)d_in[11];
    const float* b4  = (const float*)d_in[12];
    const float* b34 = (const float*)d_in[13];
    const float* b23 = (const float*)d_in[14];
    const float* b12 = (const float*)d_in[15];
    float* outp = (float*)d_out;

    float *fx_a, *fc_a, *fx_b, *fc_b;
    float *hx_a, *hc_a, *hx_b, *hc_b;
    float *qx_a, *qc_a, *qx_b, *qc_b;
    float *ex_a, *ec_a, *ex_b, *ec_b;
    cudaGetSymbolAddress((void**)&fx_a, g_fx_a);
    cudaGetSymbolAddress((void**)&fc_a, g_fc_a);
    cudaGetSymbolAddress((void**)&fx_b, g_fx_b);
    cudaGetSymbolAddress((void**)&fc_b, g_fc_b);
    cudaGetSymbolAddress((void**)&hx_a, g_hx_a);
    cudaGetSymbolAddress((void**)&hc_a, g_hc_a);
    cudaGetSymbolAddress((void**)&hx_b, g_hx_b);
    cudaGetSymbolAddress((void**)&hc_b, g_hc_b);
    cudaGetSymbolAddress((void**)&qx_a, g_qx_a);
    cudaGetSymbolAddress((void**)&qc_a, g_qc_a);
    cudaGetSymbolAddress((void**)&qx_b, g_qx_b);
    cudaGetSymbolAddress((void**)&qc_b, g_qc_b);
    cudaGetSymbolAddress((void**)&ex_a, g_ex_a);
    cudaGetSymbolAddress((void**)&ec_a, g_ec_a);
    cudaGetSymbolAddress((void**)&ex_b, g_ex_b);
    cudaGetSymbolAddress((void**)&ec_b, g_ec_b);

    void* wc_ptr;     cudaGetSymbolAddress(&wc_ptr, g_wc);
    void* stage_ptr;  cudaGetSymbolAddress(&stage_ptr, g_wstage);

    prep_kernel<<<1, 640>>>(w1, w2, w3, w34, w23, w12, w4,
                            b1, b2, b3, b34, b23, b12, b4);
    cudaMemcpyAsync(wc_ptr, stage_ptr, 640 * sizeof(unsigned long long),
                    cudaMemcpyDeviceToDevice, 0);

    auto g3 = [](int W, int H) { return dim3((W + 31) / 32, (H + 31) / 32, BB); };

    // L1: navg(w1, c0, x0)  full, CI=1
    navg5<1, false><<<g3(640, 512), 256>>>(x0, c0, 0, 0,
        fx_a, fc_a, nullptr, nullptr, 512, 640);
    // L2: navg(w2)  full
    navg5<2, false><<<g3(640, 512), 256>>>(fx_a, fc_a, 60, 2,
        fx_b, fc_b, nullptr, nullptr, 512, 640);
    // L3: navg(w3) -> (x1,c1) + fused pool -> half
    navg5<2, true><<<g3(640, 512), 256>>>(fx_b, fc_b, 180, 4,
        fx_a, fc_a, hx_a, hc_a, 512, 640);
    // L5: navg(w2)  half
    navg5<2, false><<<g3(320, 256), 256>>>(hx_a, hc_a, 60, 2,
        hx_b, hc_b, nullptr, nullptr, 256, 320);
    // L6: navg(w3) -> (x2_ds,c2_ds) + pool -> quarter
    navg5<2, true><<<g3(320, 256), 256>>>(hx_b, hc_b, 180, 4,
        hx_a, hc_a, qx_a, qc_a, 256, 320);
    // L8: navg(w2) -> (x3_ds,c3_ds) + pool -> eighth
    navg5<2, true><<<g3(160, 128), 256>>>(qx_a, qc_a, 60, 2,
        qx_b, qc_b, ex_a, ec_a, 128, 160);
    // L10: navg(w2) -> (x4_ds,c4_ds)  eighth
    navg5<2, false><<<g3(80, 64), 256>>>(ex_a, ec_a, 60, 2,
        ex_b, ec_b, nullptr, nullptr, 64, 80);
    // L12: navg(w34, cat(c3_ds, up2(c4_ds)))  quarter: full=qb, up=eb
    navg3cat<false, false><<<g3(160, 128), 256>>>(qx_b, qc_b, ex_b, ec_b,
        300, 6, qx_a, qc_a, 128, 160);
    // L14: navg(w23, cat(c2_ds, up2(c34_ds)))  half: full=ha, up=qa
    navg3cat<false, false><<<g3(320, 256), 256>>>(hx_a, hc_a, qx_a, qc_a,
        396, 8, hx_b, hc_b, 256, 320);
    // L16+L17: navg(w12, cat(up2(c23), c1)) + fused 1x1 navg(w4) -> d_out
    //          up=hb (first in concat), full=fa
    navg3cat<true, true><<<g3(640, 512), 256>>>(fx_a, fc_a, hx_b, hc_b,
        492, 10, outp, outp + (size_t)BB * H0 * W0, 512, 640);
}